// round 6
// baseline (speedup 1.0000x reference)
#include <cuda_runtime.h>
#include <cuda_bf16.h>
#include <cstdint>

#define TPB 256
#define BM 128
#define BN 128
#define BK 32
#define KU 16          // u32 (bf16x2) per row per k-tile
#define STRIDE 20      // 16 data u32 + 4 pad: all fragment LDS bank-conflict-free

// Scratch (no cudaMalloc allowed): s[b,c] = ||center_c||^2 - 2 * f_b . c_c
__device__ float g_d2[16384 * 1000];
__device__ float g_c2[4096];

// ---------------- reductions ----------------
__device__ __forceinline__ float warpReduceSum(float v) {
    #pragma unroll
    for (int o = 16; o > 0; o >>= 1) v += __shfl_xor_sync(0xffffffffu, v, o);
    return v;
}
__device__ __forceinline__ float warpReduceMin(float v) {
    #pragma unroll
    for (int o = 16; o > 0; o >>= 1) v = fminf(v, __shfl_xor_sync(0xffffffffu, v, o));
    return v;
}
__device__ __forceinline__ float warpReduceMax(float v) {
    #pragma unroll
    for (int o = 16; o > 0; o >>= 1) v = fmaxf(v, __shfl_xor_sync(0xffffffffu, v, o));
    return v;
}

__device__ __forceinline__ float blockReduceSum(float v, float* red) {
    __syncthreads();
    v = warpReduceSum(v);
    int w = threadIdx.x >> 5, l = threadIdx.x & 31;
    if (l == 0) red[w] = v;
    __syncthreads();
    if (w == 0) {
        float x = (l < (int)(blockDim.x >> 5)) ? red[l] : 0.0f;
        x = warpReduceSum(x);
        if (l == 0) red[0] = x;
    }
    __syncthreads();
    return red[0];
}
__device__ __forceinline__ float blockReduceMin(float v, float* red) {
    __syncthreads();
    v = warpReduceMin(v);
    int w = threadIdx.x >> 5, l = threadIdx.x & 31;
    if (l == 0) red[w] = v;
    __syncthreads();
    if (w == 0) {
        float x = (l < (int)(blockDim.x >> 5)) ? red[l] : 3.4e38f;
        x = warpReduceMin(x);
        if (l == 0) red[0] = x;
    }
    __syncthreads();
    return red[0];
}
__device__ __forceinline__ float blockReduceMax(float v, float* red) {
    __syncthreads();
    v = warpReduceMax(v);
    int w = threadIdx.x >> 5, l = threadIdx.x & 31;
    if (l == 0) red[w] = v;
    __syncthreads();
    if (w == 0) {
        float x = (l < (int)(blockDim.x >> 5)) ? red[l] : -3.4e38f;
        x = warpReduceMax(x);
        if (l == 0) red[0] = x;
    }
    __syncthreads();
    return red[0];
}

// ---------------- softmax over classes ----------------
__global__ void __launch_bounds__(TPB) softmax_kernel(
    const float* __restrict__ P, float* __restrict__ out, int C)
{
    __shared__ float red[8];
    int b = blockIdx.x;
    const float* row = P + (size_t)b * C;
    float v[4];
    int cnt = 0;
    float mx = -3.4e38f;
    for (int i = threadIdx.x; i < C; i += TPB) {
        float x = row[i];
        v[cnt++] = x;
        mx = fmaxf(mx, x);
    }
    mx = blockReduceMax(mx, red);
    float s = 0.0f;
    #pragma unroll
    for (int j = 0; j < 4; j++) {
        if (j < cnt) { v[j] = __expf(v[j] - mx); s += v[j]; }
    }
    s = blockReduceSum(s, red);
    float inv = 1.0f / s;
    float* orow = out + (size_t)b * C;
    cnt = 0;
    for (int i = threadIdx.x; i < C; i += TPB) orow[i] = v[cnt++] * inv;
}

// ---------------- center norms ----------------
__global__ void __launch_bounds__(TPB) c2_kernel(const float* __restrict__ Cn, int D)
{
    __shared__ float red[8];
    int c = blockIdx.x;
    const float* row = Cn + (size_t)c * D;
    float s = 0.0f;
    for (int i = threadIdx.x; i < D; i += TPB) { float x = row[i]; s += x * x; }
    s = blockReduceSum(s, red);
    if (threadIdx.x == 0) g_c2[c] = s;
}

// ---------------- bf16 mma GEMM: s[b,c] = c2[c] - 2 * f_b . c_c ----------------
__device__ __forceinline__ void mma_bf16(float* c, const uint32_t* a, const uint32_t* b)
{
    asm volatile(
        "mma.sync.aligned.m16n8k16.row.col.f32.bf16.bf16.f32 "
        "{%0,%1,%2,%3},{%4,%5,%6,%7},{%8,%9},{%0,%1,%2,%3};\n"
        : "+f"(c[0]), "+f"(c[1]), "+f"(c[2]), "+f"(c[3])
        : "r"(a[0]), "r"(a[1]), "r"(a[2]), "r"(a[3]), "r"(b[0]), "r"(b[1]));
}

__device__ __forceinline__ uint32_t pack_bf16(float x, float y)
{
    __nv_bfloat162 h = __float22bfloat162_rn(make_float2(x, y));
    return *reinterpret_cast<uint32_t*>(&h);
}

__global__ void __launch_bounds__(TPB) gemm_mindist_kernel(
    const float* __restrict__ F, const float* __restrict__ Cn,
    int Bsz, int C, int D)
{
    __shared__ uint32_t As[2][BM * STRIDE];   // bf16x2 packed, double-buffered
    __shared__ uint32_t Bs[2][BN * STRIDE];

    const int tid  = threadIdx.x;
    const int bm   = blockIdx.y * BM;
    const int bn   = blockIdx.x * BN;
    const int lane = tid & 31;
    const int warp = tid >> 5;
    const int wm   = warp & 3;   // 4 warps in M -> 32 rows each
    const int wn   = warp >> 2;  // 2 warps in N -> 64 cols each
    const int gr   = lane >> 2;
    const int tg   = lane & 3;

    float acc[2][8][4];
    #pragma unroll
    for (int mt = 0; mt < 2; mt++)
        #pragma unroll
        for (int nt = 0; nt < 8; nt++)
            #pragma unroll
            for (int k = 0; k < 4; k++) acc[mt][nt][k] = 0.0f;

    const int nk = D / BK;   // 64
    uint2 ar[4], br[4];

    auto gload = [&](int kt) {
        #pragma unroll
        for (int j = 0; j < 4; j++) {
            int i  = tid + TPB * j;
            int r  = i >> 3;
            int c4 = (i & 7) * 4;
            float4 t = *(const float4*)(F + (size_t)(bm + r) * D + kt * BK + c4);
            ar[j].x = pack_bf16(t.x, t.y);
            ar[j].y = pack_bf16(t.z, t.w);
            int brow = bn + r;
            if (brow < C) {
                float4 u = *(const float4*)(Cn + (size_t)brow * D + kt * BK + c4);
                br[j].x = pack_bf16(u.x, u.y);
                br[j].y = pack_bf16(u.z, u.w);
            } else {
                br[j].x = 0u; br[j].y = 0u;
            }
        }
    };
    auto sstore = [&](int buf) {
        #pragma unroll
        for (int j = 0; j < 4; j++) {
            int i  = tid + TPB * j;
            int r  = i >> 3;
            int k2 = (i & 7) * 2;
            *(uint2*)&As[buf][r * STRIDE + k2] = ar[j];
            *(uint2*)&Bs[buf][r * STRIDE + k2] = br[j];
        }
    };

    gload(0);
    sstore(0);
    __syncthreads();

    for (int kt = 0; kt < nk; kt++) {
        const int buf = kt & 1;
        if (kt + 1 < nk) gload(kt + 1);

        const uint32_t* Ab = &As[buf][(wm * 32) * STRIDE];
        const uint32_t* Bb = &Bs[buf][(wn * 64) * STRIDE];

        #pragma unroll
        for (int ks = 0; ks < 2; ks++) {
            const int off = ks * 8;
            uint32_t a[2][4];
            #pragma unroll
            for (int mt = 0; mt < 2; mt++) {
                a[mt][0] = Ab[(mt * 16 + gr)     * STRIDE + off + tg];
                a[mt][1] = Ab[(mt * 16 + gr + 8) * STRIDE + off + tg];
                a[mt][2] = Ab[(mt * 16 + gr)     * STRIDE + off + tg + 4];
                a[mt][3] = Ab[(mt * 16 + gr + 8) * STRIDE + off + tg + 4];
            }
            uint32_t bb[8][2];
            #pragma unroll
            for (int nt = 0; nt < 8; nt++) {
                bb[nt][0] = Bb[(nt * 8 + gr) * STRIDE + off + tg];
                bb[nt][1] = Bb[(nt * 8 + gr) * STRIDE + off + tg + 4];
            }
            #pragma unroll
            for (int mt = 0; mt < 2; mt++)
                #pragma unroll
                for (int nt = 0; nt < 8; nt++)
                    mma_bf16(acc[mt][nt], a[mt], bb[nt]);
        }

        if (kt + 1 < nk) {
            sstore(buf ^ 1);   // write other buffer: no hazard with current readers
            __syncthreads();   // single barrier per k-tile
        }
    }

    // epilogue: s = c2[c] - 2*cross  (m16n8k16 D layout == m16n8k8: (gr,2tg),(gr,2tg+1),(gr+8,..))
    #pragma unroll
    for (int mt = 0; mt < 2; mt++) {
        #pragma unroll
        for (int nt = 0; nt < 8; nt++) {
            int r0 = bm + wm * 32 + mt * 16 + gr;
            int c0 = bn + wn * 64 + nt * 8 + 2 * tg;
            if (c0 < C) {
                float cc = g_c2[c0];
                g_d2[(size_t)r0 * C + c0]       = cc - 2.0f * acc[mt][nt][0];
                g_d2[(size_t)(r0 + 8) * C + c0] = cc - 2.0f * acc[mt][nt][2];
            }
            if (c0 + 1 < C) {
                float cc = g_c2[c0 + 1];
                g_d2[(size_t)r0 * C + c0 + 1]       = cc - 2.0f * acc[mt][nt][1];
                g_d2[(size_t)(r0 + 8) * C + c0 + 1] = cc - 2.0f * acc[mt][nt][3];
            }
        }
    }
}

// ---------------- min + exact fp32 refinement + threshold mask ----------------
#define MARGIN 4.0f

__global__ void __launch_bounds__(TPB) minmask_kernel(
    const float* __restrict__ F, const float* __restrict__ Cn,
    const float* __restrict__ GS, float* __restrict__ mask, int C, int D)
{
    __shared__ float sfeat[2048];
    __shared__ float red[8];
    __shared__ int   s_cand[64];
    __shared__ int   s_ncand;

    const int b   = blockIdx.x;
    const int tid = threadIdx.x;

    // vectorized feature load + ||f||^2 (D == 2048 here; fallback loop for safety)
    float f2p = 0.0f;
    if ((D & 3) == 0) {
        const float4* F4 = (const float4*)(F + (size_t)b * D);
        for (int i = tid; i < (D >> 2); i += TPB) {
            float4 v = F4[i];
            int k = i * 4;
            sfeat[k] = v.x; sfeat[k+1] = v.y; sfeat[k+2] = v.z; sfeat[k+3] = v.w;
            f2p += v.x*v.x + v.y*v.y + v.z*v.z + v.w*v.w;
        }
    } else {
        for (int i = tid; i < D; i += TPB) {
            float v = F[(size_t)b * D + i];
            sfeat[i] = v;
            f2p += v * v;
        }
    }
    float f2 = blockReduceSum(f2p, red);

    const float* srow = g_d2 + (size_t)b * C;
    float mn = 3.4e38f;
    for (int i = tid; i < C; i += TPB) mn = fminf(mn, srow[i]);
    mn = blockReduceMin(mn, red);

    if (tid == 0) s_ncand = 0;
    __syncthreads();
    for (int i = tid; i < C; i += TPB) {
        if (srow[i] <= mn + MARGIN) {
            int j = atomicAdd(&s_ncand, 1);
            if (j < 64) s_cand[j] = i;
        }
    }
    __syncthreads();
    int nc = min(s_ncand, 64);

    // exact fp32 recompute of candidate distances (kills bf16 noise at the decision)
    float best = 3.4e38f;
    for (int j = 0; j < nc; j++) {
        int c = s_cand[j];
        const float* crow = Cn + (size_t)c * D;
        float dp = 0.0f;
        for (int i = tid; i < D; i += TPB) dp += sfeat[i] * crow[i];
        float dot = blockReduceSum(dp, red);
        best = fminf(best, g_c2[c] - 2.0f * dot);
    }

    if (tid == 0) {
        float d2   = f2 + best;
        float dist = sqrtf(fmaxf(d2, 0.0f));
        float T    = GS[0] + 1.5f * GS[1];
        mask[b] = (dist / (T + 1e-8f) > 1.0f) ? 1.0f : 0.0f;
    }
}

__global__ void fill_kernel(float* p, int n)
{
    int i = blockIdx.x * blockDim.x + threadIdx.x;
    if (i < n) p[i] = 0.0f;
}

// ---------------- launch ----------------
extern "C" void kernel_launch(void* const* d_in, const int* in_sizes, int n_in,
                              void* d_out, int out_size)
{
    const float* F  = (const float*)d_in[0];  // features  [B, D]
    const float* P  = (const float*)d_in[1];  // predictions [B, C]
    const float* Cn = (const float*)d_in[2];  // centers [C, D]
    const float* GS = (const float*)d_in[3];  // global_stats [2]

    const int B = in_sizes[4];            // known_labels length
    const int D = in_sizes[0] / B;
    const int C = in_sizes[1] / B;

    float* out   = (float*)d_out;
    float* mask  = out;                   // mask_novel first (return order)
    float* probs = out + B;               // probs second

    softmax_kernel<<<B, TPB>>>(P, probs, C);
    c2_kernel<<<C, TPB>>>(Cn, D);

    dim3 g((C + BN - 1) / BN, B / BM);    // B=16384 divisible by 128; D=2048 by 32
    gemm_mindist_kernel<<<g, TPB>>>(F, Cn, B, C, D);

    minmask_kernel<<<B, TPB>>>(F, Cn, GS, mask, C, D);

    long total = (long)B * C + B;
    if ((long)out_size > total) {
        long rem = (long)out_size - total;
        fill_kernel<<<(int)((rem + 255) / 256), 256>>>(out + total, (int)rem);
    }
}